// round 11
// baseline (speedup 1.0000x reference)
#include <cuda_runtime.h>
#include <cstdint>

// ---------------------------------------------------------------------------
// Noise2Void masked-MSE, exact replication of the JAX reference with
// jax.random.key(42) under the PARTITIONABLE threefry scheme (JAX >= 0.5
// default: jax_threefry_partitionable=True).
//
// Loss collapses to hot pixels only:
//   loss = sum_t (x[n,c,ry,rx] - x[n,c,hy,hx])^2 / (N*C*K)
//
// Single kernel, single packed-integer atomic for the global reduction:
//   g_acc += (1 << 54) | trunc(block_sum * 2^32)
// Integer adds are associative -> bitwise-deterministic result independent of
// block arrival order. The block seeing prev>>54 == NBLK-1 holds the total
// in-register, writes out[0], and resets g_acc (replay-idempotent).
// Latency-trimmed: fp32 fixed-point convert, reciprocal-LUT div (sh1 in
// {3,4,5}), 128-thread blocks over all SMs.
// ---------------------------------------------------------------------------

#define N_  32
#define C_  3
#define H_  512
#define W_  512
#define ITEMS 24576       // N_*C_*256
#define TPB  128
#define NBLK 192          // ITEMS / TPB

#define CNT_SHIFT 54
#define SUM_MASK  ((1ULL << CNT_SHIFT) - 1ULL)

__device__ unsigned long long g_acc = 0ULL;

__host__ __device__ __forceinline__ uint32_t rotl32(uint32_t v, int r)
{
#ifdef __CUDA_ARCH__
    return __funnelshift_l(v, v, r);
#else
    return (v << r) | (v >> (32 - r));
#endif
}

__host__ __device__ __forceinline__ void threefry2x32(
    uint32_t k0, uint32_t k1, uint32_t x0, uint32_t x1,
    uint32_t &o0, uint32_t &o1)
{
    const uint32_t ks0 = k0, ks1 = k1, ks2 = k0 ^ k1 ^ 0x1BD11BDAu;
    x0 += ks0; x1 += ks1;
#define TF_R4(a,b,c,d)                                   \
    x0 += x1; x1 = rotl32(x1,(a)); x1 ^= x0;             \
    x0 += x1; x1 = rotl32(x1,(b)); x1 ^= x0;             \
    x0 += x1; x1 = rotl32(x1,(c)); x1 ^= x0;             \
    x0 += x1; x1 = rotl32(x1,(d)); x1 ^= x0;
    TF_R4(13,15,26, 6)  x0 += ks1; x1 += ks2 + 1u;
    TF_R4(17,29,16,24)  x0 += ks2; x1 += ks0 + 2u;
    TF_R4(13,15,26, 6)  x0 += ks0; x1 += ks1 + 3u;
    TF_R4(17,29,16,24)  x0 += ks1; x1 += ks2 + 4u;
    TF_R4(13,15,26, 6)  x0 += ks2; x1 += ks0 + 5u;
#undef TF_R4
    o0 = x0; o1 = x1;
}

// partitionable random_bits: 32-bit element i = o0 ^ o1 of block (0, i)
__device__ __forceinline__ uint32_t rb32(uint32_t k0, uint32_t k1, uint32_t i)
{
    uint32_t o0, o1;
    threefry2x32(k0, k1, 0u, i, o0, o1);
    return o0 ^ o1;
}

__device__ __forceinline__ float warp_sum(float v)
{
#pragma unroll
    for (int o = 16; o > 0; o >>= 1)
        v += __shfl_down_sync(0xFFFFFFFFu, v, o);
    return v;
}

__global__ void __launch_bounds__(TPB)
n2v_fused(const float* __restrict__ x, float* __restrict__ out,
          uint32_t kl0, uint32_t kl1,   // randint lower-bits key
          uint32_t ku0, uint32_t ku1)   // uniform key (k2)
{
    const int tid  = threadIdx.x;
    const int lane = tid & 31;
    const int wid  = tid >> 5;
    const int t    = blockIdx.x * TPB + tid;   // item index in [0, ITEMS)

    // --- Phase 1: offset RNG (y, x) -> hot pixel; issue its load early ---
    uint32_t oy = rb32(kl0, kl1, (uint32_t)(2 * t));
    uint32_t ox = rb32(kl0, kl1, (uint32_t)(2 * t + 1));

    int nc = t >> 8;            // n*C + c
    int k  = t & 255;
    int by = k >> 4;
    int bx = k & 15;

    int hy = by * 32 + (int)(oy & 31u);
    int hx = bx * 32 + (int)(ox & 31u);

    const float* img = x + (size_t)nc * (H_ * W_);
    float b = __ldg(img + hy * W_ + hx);      // long-scoreboard hidden below

    // ROI bounds (independent of the uniform draw), faithful quirk:
    // roimax = min(hc+3, shape-1)
    int rmin0 = max(hy - 2, 0);
    int rmax0 = min(hy + 3, H_ - 1);
    int rmin1 = max(hx - 2, 0);
    int rmax1 = min(hx + 3, W_ - 1);
    int sh0 = rmax0 - rmin0;
    int sh1 = rmax1 - rmin1;           // in {3,4,5}

    bool hasc = (sh0 > 2) && (sh1 > 2);
    int m = sh0 * sh1 - (hasc ? 1 : 0);

    // --- Phase 2: uniform RNG -> replacement pixel ---
    uint32_t ub = rb32(ku0, ku1, (uint32_t)t);

    // uniform in [0,1): bitcast((bits>>9)|0x3f800000) - 1.0
    float uf = __uint_as_float((ub >> 9) | 0x3f800000u) - 1.0f;
    int u = __float2int_rd(uf * (float)m);   // floor, u in [0, m]
    u = min(u, m - 1);
    int cflat = 2 * sh1 + 2;                 // flat index of rc=(2,2)
    if (hasc && u >= cflat) u += 1;

    // u / sh1, u % sh1 via exact reciprocal (sh1 in {3,4,5}, u <= 24):
    // RN reciprocals all round >= true value -> truncation is exact here.
    float rcp = (sh1 == 3) ? __uint_as_float(0x3EAAAAABu)      // 1/3 (up)
              : (sh1 == 4) ? 0.25f                              // exact
                           : __uint_as_float(0x3E4CCCCDu);      // 1/5 (up)
    int q = __float2int_rz((float)u * rcp);
    int r = u - q * sh1;

    int ry = rmin0 + q;
    int rx = rmin1 + r;

    float a = __ldg(img + ry * W_ + rx);
    float d = a - b;

    // ---- block reduction (deterministic fixed tree) ----
    float v = warp_sum(d * d);
    __shared__ float wsum[TPB / 32];
    if (lane == 0) wsum[wid] = v;
    __syncthreads();

    if (tid == 0) {
        float s = (wsum[0] + wsum[1]) + (wsum[2] + wsum[3]);

        // fixed-point (2^-32) contribution; fp32 convert (block sums < 2^14,
        // quantization error ~2^-24 rel per block -> ~1e-7 rel total, ok)
        unsigned long long contrib =
            (unsigned long long)(s * 4294967296.0f);
        unsigned long long prev =
            atomicAdd(&g_acc, (1ULL << CNT_SHIFT) + contrib);

        if ((prev >> CNT_SHIFT) == (unsigned long long)(NBLK - 1)) {
            // all other blocks' atomics have completed; total is in-register
            unsigned long long total = ((prev & SUM_MASK) + contrib) & SUM_MASK;
            g_acc = 0ULL;  // reset for next graph replay (race-free: we're last)
            // scale = 2^-32 (undo fixed point) / 24576 (mask.sum())
            out[0] = (float)((double)total * (1.0 / 4294967296.0) / 24576.0);
        }
    }
}

extern "C" void kernel_launch(void* const* d_in, const int* in_sizes, int n_in,
                              void* d_out, int out_size)
{
    (void)in_sizes; (void)n_in; (void)out_size;
    const float* x = (const float*)d_in[0];
    float* out = (float*)d_out;

    // ---- Derive JAX keys on host (pure CPU math, graph-capture safe) ----
    // root = key(42) = (0, 42)
    uint32_t A0, A1, B0, B1;
    // split(root, 2) foldlike: sub-key i = full block threefry(root; 0, i)
    threefry2x32(0u, 42u, 0u, 0u, A0, A1);   // k1 (randint key)
    threefry2x32(0u, 42u, 0u, 1u, B0, B1);   // k2 (uniform key)

    // randint internally splits k1 (foldlike); lower_bits uses the SECOND
    // sub-key = threefry(k1; 0, 1). (higher-bits key unused: (2^16 % 32)^2 % 32 = 0)
    uint32_t kl0, kl1;
    threefry2x32(A0, A1, 0u, 1u, kl0, kl1);

    n2v_fused<<<NBLK, TPB>>>(x, out, kl0, kl1, B0, B1);
}

// round 12
// speedup vs baseline: 1.0048x; 1.0048x over previous
#include <cuda_runtime.h>
#include <cstdint>

// ---------------------------------------------------------------------------
// Noise2Void masked-MSE, exact replication of the JAX reference with
// jax.random.key(42) under the PARTITIONABLE threefry scheme (JAX >= 0.5
// default: jax_threefry_partitionable=True).
//
// Loss collapses to hot pixels only:
//   loss = sum_t (x[n,c,ry,rx] - x[n,c,hy,hx])^2 / (N*C*K)
//
// Single kernel, single packed-integer atomic for the global reduction:
//   g_acc += (1 << 54) | trunc(block_sum * 2^32)
// Integer adds are associative -> bitwise-deterministic result independent of
// block arrival order. The block seeing prev>>54 == NBLK-1 holds the total
// in-register, writes out[0], and resets g_acc (replay-idempotent).
//
// ROI divisor sh1 ranges over {2,3,4,5} (2 occurs at hx==511 via the
// roimax=min(hc+3, shape-1) clamp) -- the reciprocal LUT covers all four,
// with round-up reciprocals proven exact for truncating division at u <= 24.
// ---------------------------------------------------------------------------

#define N_  32
#define C_  3
#define H_  512
#define W_  512
#define ITEMS 24576       // N_*C_*256
#define TPB  128
#define NBLK 192          // ITEMS / TPB

#define CNT_SHIFT 54
#define SUM_MASK  ((1ULL << CNT_SHIFT) - 1ULL)

__device__ unsigned long long g_acc = 0ULL;

__host__ __device__ __forceinline__ uint32_t rotl32(uint32_t v, int r)
{
#ifdef __CUDA_ARCH__
    return __funnelshift_l(v, v, r);
#else
    return (v << r) | (v >> (32 - r));
#endif
}

__host__ __device__ __forceinline__ void threefry2x32(
    uint32_t k0, uint32_t k1, uint32_t x0, uint32_t x1,
    uint32_t &o0, uint32_t &o1)
{
    const uint32_t ks0 = k0, ks1 = k1, ks2 = k0 ^ k1 ^ 0x1BD11BDAu;
    x0 += ks0; x1 += ks1;
#define TF_R4(a,b,c,d)                                   \
    x0 += x1; x1 = rotl32(x1,(a)); x1 ^= x0;             \
    x0 += x1; x1 = rotl32(x1,(b)); x1 ^= x0;             \
    x0 += x1; x1 = rotl32(x1,(c)); x1 ^= x0;             \
    x0 += x1; x1 = rotl32(x1,(d)); x1 ^= x0;
    TF_R4(13,15,26, 6)  x0 += ks1; x1 += ks2 + 1u;
    TF_R4(17,29,16,24)  x0 += ks2; x1 += ks0 + 2u;
    TF_R4(13,15,26, 6)  x0 += ks0; x1 += ks1 + 3u;
    TF_R4(17,29,16,24)  x0 += ks1; x1 += ks2 + 4u;
    TF_R4(13,15,26, 6)  x0 += ks2; x1 += ks0 + 5u;
#undef TF_R4
    o0 = x0; o1 = x1;
}

// partitionable random_bits: 32-bit element i = o0 ^ o1 of block (0, i)
__device__ __forceinline__ uint32_t rb32(uint32_t k0, uint32_t k1, uint32_t i)
{
    uint32_t o0, o1;
    threefry2x32(k0, k1, 0u, i, o0, o1);
    return o0 ^ o1;
}

__device__ __forceinline__ float warp_sum(float v)
{
#pragma unroll
    for (int o = 16; o > 0; o >>= 1)
        v += __shfl_down_sync(0xFFFFFFFFu, v, o);
    return v;
}

__global__ void __launch_bounds__(TPB)
n2v_fused(const float* __restrict__ x, float* __restrict__ out,
          uint32_t kl0, uint32_t kl1,   // randint lower-bits key
          uint32_t ku0, uint32_t ku1)   // uniform key (k2)
{
    const int tid  = threadIdx.x;
    const int lane = tid & 31;
    const int wid  = tid >> 5;
    const int t    = blockIdx.x * TPB + tid;   // item index in [0, ITEMS)

    // --- Phase 1: offset RNG (y, x) -> hot pixel; issue its load early ---
    uint32_t oy = rb32(kl0, kl1, (uint32_t)(2 * t));
    uint32_t ox = rb32(kl0, kl1, (uint32_t)(2 * t + 1));

    int nc = t >> 8;            // n*C + c
    int k  = t & 255;
    int by = k >> 4;
    int bx = k & 15;

    int hy = by * 32 + (int)(oy & 31u);
    int hx = bx * 32 + (int)(ox & 31u);

    const float* img = x + (size_t)nc * (H_ * W_);
    float b = __ldg(img + hy * W_ + hx);      // long-scoreboard hidden below

    // ROI bounds (independent of the uniform draw), faithful quirk:
    // roimax = min(hc+3, shape-1)  ->  sh in {2,3,4,5} (2 at coord 511)
    int rmin0 = max(hy - 2, 0);
    int rmax0 = min(hy + 3, H_ - 1);
    int rmin1 = max(hx - 2, 0);
    int rmax1 = min(hx + 3, W_ - 1);
    int sh0 = rmax0 - rmin0;
    int sh1 = rmax1 - rmin1;           // in {2,3,4,5}

    bool hasc = (sh0 > 2) && (sh1 > 2);
    int m = sh0 * sh1 - (hasc ? 1 : 0);

    // --- Phase 2: uniform RNG -> replacement pixel ---
    uint32_t ub = rb32(ku0, ku1, (uint32_t)t);

    // uniform in [0,1): bitcast((bits>>9)|0x3f800000) - 1.0
    float uf = __uint_as_float((ub >> 9) | 0x3f800000u) - 1.0f;
    int u = __float2int_rd(uf * (float)m);   // floor, u in [0, m-1]
    u = min(u, m - 1);
    int cflat = 2 * sh1 + 2;                 // flat index of rc=(2,2)
    if (hasc && u >= cflat) u += 1;

    // u / sh1, u % sh1 via exact reciprocal (sh1 in {2,3,4,5}, u <= 24):
    // 0.5 and 0.25 exact; 1/3 and 1/5 RN round UP -> truncation exact:
    //   exact multiples u=q*sh1 give products that round back to q exactly,
    //   non-multiples sit >= 0.2 below the next integer (checked all u<=24).
    float rcp = (sh1 <= 3) ? ((sh1 == 2) ? 0.5f
                                         : __uint_as_float(0x3EAAAAABu))  // 1/3
              : ((sh1 == 4) ? 0.25f
                            : __uint_as_float(0x3E4CCCCDu));              // 1/5
    int q = __float2int_rz((float)u * rcp);
    int r = u - q * sh1;

    int ry = rmin0 + q;
    int rx = rmin1 + r;

    float a = __ldg(img + ry * W_ + rx);
    float d = a - b;

    // ---- block reduction (deterministic fixed tree) ----
    float v = warp_sum(d * d);
    __shared__ float wsum[TPB / 32];
    if (lane == 0) wsum[wid] = v;
    __syncthreads();

    if (tid == 0) {
        float s = (wsum[0] + wsum[1]) + (wsum[2] + wsum[3]);

        // fixed-point (2^-32) contribution. s ~ 2^8 with fp32 mantissa:
        // s * 2^32 is an exactly-representable integer -> conversion exact.
        unsigned long long contrib =
            (unsigned long long)(s * 4294967296.0f);
        unsigned long long prev =
            atomicAdd(&g_acc, (1ULL << CNT_SHIFT) + contrib);

        if ((prev >> CNT_SHIFT) == (unsigned long long)(NBLK - 1)) {
            // all other blocks' atomics have completed; total is in-register
            unsigned long long total = ((prev & SUM_MASK) + contrib) & SUM_MASK;
            g_acc = 0ULL;  // reset for next graph replay (race-free: we're last)
            // scale = 2^-32 (undo fixed point) / 24576 (mask.sum());
            // u64->f32 direct convert: <=2^-24 rel rounding, negligible.
            out[0] = (float)total * (1.0f / 4294967296.0f / 24576.0f);
        }
    }
}

extern "C" void kernel_launch(void* const* d_in, const int* in_sizes, int n_in,
                              void* d_out, int out_size)
{
    (void)in_sizes; (void)n_in; (void)out_size;
    const float* x = (const float*)d_in[0];
    float* out = (float*)d_out;

    // ---- Derive JAX keys on host (pure CPU math, graph-capture safe) ----
    // root = key(42) = (0, 42)
    uint32_t A0, A1, B0, B1;
    // split(root, 2) foldlike: sub-key i = full block threefry(root; 0, i)
    threefry2x32(0u, 42u, 0u, 0u, A0, A1);   // k1 (randint key)
    threefry2x32(0u, 42u, 0u, 1u, B0, B1);   // k2 (uniform key)

    // randint internally splits k1 (foldlike); lower_bits uses the SECOND
    // sub-key = threefry(k1; 0, 1). (higher-bits key unused: (2^16 % 32)^2 % 32 = 0)
    uint32_t kl0, kl1;
    threefry2x32(A0, A1, 0u, 1u, kl0, kl1);

    n2v_fused<<<NBLK, TPB>>>(x, out, kl0, kl1, B0, B1);
}